// round 1
// baseline (speedup 1.0000x reference)
#include <cuda_runtime.h>
#include <cstdint>
#include <cmath>

// ---------------------------------------------------------------------------
// Head_55671366091048:  q = x Wq^T ; k = y Wk^T ; v = y Wv^T
//                       a = (q k^T) / sqrt(512), zero where j >= i (strict)
//                       out = a v
// Shapes: x[8192,2048] y[8192,2048] Wq/Wk/Wv[512,2048] -> out[8192,512] (f32)
//
// Round 0 baseline: TF32 mma.sync (m16n8k8) tiled GEMMs, f32 accumulate.
//   - 3x NT GEMM (qkv), 1x NT GEMM w/ causal-strict mask + block skip (a),
//     1x NN GEMM w/ per-row-block K limit (out).
//   - Scratch in __device__ globals (no allocations anywhere).
// ---------------------------------------------------------------------------

namespace {
constexpr int kNX = 8192;
constexpr int kNY = 8192;
constexpr int kC  = 2048;
constexpr int kD  = 512;

constexpr int BM = 128;
constexpr int BN = 128;
constexpr int BK = 16;
constexpr int ASTR = BK + 4;   // 20 floats/row: conflict-free fragment LDS
constexpr int BSTR = BN + 8;   // 136 floats/row: conflict-free for NN B frags
}  // namespace

__device__ float g_q[(size_t)kNX * kD];
__device__ float g_k[(size_t)kNY * kD];
__device__ float g_v[(size_t)kNY * kD];
__device__ float g_a[(size_t)kNX * kNY];   // 256 MB scratch (lower blocks only)

__device__ __forceinline__ float tf32r(float f) {
  uint32_t u;
  asm("cvt.rna.tf32.f32 %0, %1;" : "=r"(u) : "f"(f));
  return __uint_as_float(u);
}
__device__ __forceinline__ float4 tf32r4(float4 v) {
  return make_float4(tf32r(v.x), tf32r(v.y), tf32r(v.z), tf32r(v.w));
}
__device__ __forceinline__ void mma8(float* c, const uint32_t* a, const uint32_t* b) {
  asm volatile(
      "mma.sync.aligned.m16n8k8.row.col.f32.tf32.tf32.f32 "
      "{%0,%1,%2,%3}, {%4,%5,%6,%7}, {%8,%9}, {%0,%1,%2,%3};\n"
      : "+f"(c[0]), "+f"(c[1]), "+f"(c[2]), "+f"(c[3])
      : "r"(a[0]), "r"(a[1]), "r"(a[2]), "r"(a[3]), "r"(b[0]), "r"(b[1]));
}

// ---------------------------------------------------------------------------
// NT GEMM: C[M,N] = A[M,K] * B[N,K]^T  (A,B row-major, K contiguous)
// MODE 0: plain f32 store.
// MODE 1: skip blocks with bn>bm; epilogue val = (j>=i) ? 0 : val*scale.
// ---------------------------------------------------------------------------
template <int MODE>
__global__ void __launch_bounds__(256, 2)
gemm_nt(const float* __restrict__ A, const float* __restrict__ B,
        float* __restrict__ C, int M, int N, int K, float scale) {
  const int bm = blockIdx.y, bn = blockIdx.x;
  if (MODE == 1 && bn > bm) return;

  __shared__ float As[2][BM * ASTR];
  __shared__ float Bs[2][BN * ASTR];

  const int tid = threadIdx.x;
  const int row0 = bm * BM, col0 = bn * BN;

  // global->smem mapping: 512 float4 per 128x16 tile, 2 per thread
  const int lr = tid >> 2;
  const int lc = (tid & 3) * 4;
  const float* Ag0 = A + (size_t)(row0 + lr) * K + lc;
  const float* Ag1 = A + (size_t)(row0 + lr + 64) * K + lc;
  const float* Bg0 = B + (size_t)(col0 + lr) * K + lc;
  const float* Bg1 = B + (size_t)(col0 + lr + 64) * K + lc;

  const int lane = tid & 31, wid = tid >> 5;
  const int wm = (wid & 3) * 32;   // warp tile 32x64
  const int wn = (wid >> 2) * 64;
  const int grp = lane >> 2, tig = lane & 3;

  float acc[2][8][4];
#pragma unroll
  for (int i = 0; i < 2; i++)
#pragma unroll
    for (int j = 0; j < 8; j++)
#pragma unroll
      for (int l = 0; l < 4; l++) acc[i][j][l] = 0.f;

  float4 pa0 = *(const float4*)Ag0;
  float4 pa1 = *(const float4*)Ag1;
  float4 pb0 = *(const float4*)Bg0;
  float4 pb1 = *(const float4*)Bg1;

  *(float4*)&As[0][lr * ASTR + lc]        = tf32r4(pa0);
  *(float4*)&As[0][(lr + 64) * ASTR + lc] = tf32r4(pa1);
  *(float4*)&Bs[0][lr * ASTR + lc]        = tf32r4(pb0);
  *(float4*)&Bs[0][(lr + 64) * ASTR + lc] = tf32r4(pb1);
  __syncthreads();

  const int nT = K / BK;
  int cur = 0;
  for (int t = 0; t < nT; ++t) {
    if (t + 1 < nT) {
      const int ko = (t + 1) * BK;
      pa0 = *(const float4*)(Ag0 + ko);
      pa1 = *(const float4*)(Ag1 + ko);
      pb0 = *(const float4*)(Bg0 + ko);
      pb1 = *(const float4*)(Bg1 + ko);
    }
#pragma unroll
    for (int kk = 0; kk < BK; kk += 8) {
      uint32_t af[2][4];
#pragma unroll
      for (int mf = 0; mf < 2; ++mf) {
        const float* ap = &As[cur][(wm + mf * 16 + grp) * ASTR + kk + tig];
        af[mf][0] = __float_as_uint(ap[0]);
        af[mf][1] = __float_as_uint(ap[8 * ASTR]);
        af[mf][2] = __float_as_uint(ap[4]);
        af[mf][3] = __float_as_uint(ap[8 * ASTR + 4]);
      }
#pragma unroll
      for (int nf = 0; nf < 8; ++nf) {
        const float* bp = &Bs[cur][(wn + nf * 8 + grp) * ASTR + kk + tig];
        uint32_t bf[2];
        bf[0] = __float_as_uint(bp[0]);
        bf[1] = __float_as_uint(bp[4]);
        mma8(acc[0][nf], af[0], bf);
        mma8(acc[1][nf], af[1], bf);
      }
    }
    if (t + 1 < nT) {
      const int nxt = cur ^ 1;
      *(float4*)&As[nxt][lr * ASTR + lc]        = tf32r4(pa0);
      *(float4*)&As[nxt][(lr + 64) * ASTR + lc] = tf32r4(pa1);
      *(float4*)&Bs[nxt][lr * ASTR + lc]        = tf32r4(pb0);
      *(float4*)&Bs[nxt][(lr + 64) * ASTR + lc] = tf32r4(pb1);
      __syncthreads();
      cur = nxt;
    }
  }

#pragma unroll
  for (int mf = 0; mf < 2; ++mf)
#pragma unroll
    for (int nf = 0; nf < 8; ++nf) {
      const int r = row0 + wm + mf * 16 + grp;
      const int c = col0 + wn + nf * 8 + tig * 2;
      float v0 = acc[mf][nf][0], v1 = acc[mf][nf][1];
      float v2 = acc[mf][nf][2], v3 = acc[mf][nf][3];
      if (MODE == 1) {
        v0 = (c     >= r)     ? 0.f : v0 * scale;
        v1 = (c + 1 >= r)     ? 0.f : v1 * scale;
        v2 = (c     >= r + 8) ? 0.f : v2 * scale;
        v3 = (c + 1 >= r + 8) ? 0.f : v3 * scale;
      }
      float* cp = C + (size_t)r * N + c;
      cp[0] = v0;
      cp[1] = v1;
      cp[(size_t)8 * N]     = v2;
      cp[(size_t)8 * N + 1] = v3;
    }
}

// ---------------------------------------------------------------------------
// NN GEMM: C[M,N] = A[M,K] * B[K,N]  (row-major; lda == K, ldb == N)
// TRI 1: K limited to (bm+1)*BM per row-block (strict causal chain).
// ---------------------------------------------------------------------------
template <int TRI>
__global__ void __launch_bounds__(256, 2)
gemm_nn(const float* __restrict__ A, const float* __restrict__ B,
        float* __restrict__ C, int M, int N, int K) {
  const int bm = blockIdx.y, bn = blockIdx.x;
  const int Keff = TRI ? min(K, (bm + 1) * BM) : K;

  __shared__ float As[2][BM * ASTR];
  __shared__ float Bs[2][BK * BSTR];

  const int tid = threadIdx.x;
  const int row0 = bm * BM, col0 = bn * BN;

  const int lr = tid >> 2, lc = (tid & 3) * 4;
  const float* Ag0 = A + (size_t)(row0 + lr) * K + lc;
  const float* Ag1 = A + (size_t)(row0 + lr + 64) * K + lc;

  const int bk = tid >> 5;         // 0..7
  const int bc = (tid & 31) * 4;   // 0..124
  const float* Bg0 = B + (size_t)bk * N + col0 + bc;
  const float* Bg1 = B + (size_t)(bk + 8) * N + col0 + bc;

  const int lane = tid & 31, wid = tid >> 5;
  const int wm = (wid & 3) * 32;
  const int wn = (wid >> 2) * 64;
  const int grp = lane >> 2, tig = lane & 3;

  float acc[2][8][4];
#pragma unroll
  for (int i = 0; i < 2; i++)
#pragma unroll
    for (int j = 0; j < 8; j++)
#pragma unroll
      for (int l = 0; l < 4; l++) acc[i][j][l] = 0.f;

  float4 pa0 = *(const float4*)Ag0;
  float4 pa1 = *(const float4*)Ag1;
  float4 pb0 = *(const float4*)Bg0;
  float4 pb1 = *(const float4*)Bg1;

  *(float4*)&As[0][lr * ASTR + lc]        = tf32r4(pa0);
  *(float4*)&As[0][(lr + 64) * ASTR + lc] = tf32r4(pa1);
  *(float4*)&Bs[0][bk * BSTR + bc]        = tf32r4(pb0);
  *(float4*)&Bs[0][(bk + 8) * BSTR + bc]  = tf32r4(pb1);
  __syncthreads();

  const int nT = Keff / BK;
  int cur = 0;
  for (int t = 0; t < nT; ++t) {
    if (t + 1 < nT) {
      const size_t ko = (size_t)(t + 1) * BK;
      pa0 = *(const float4*)(Ag0 + ko);
      pa1 = *(const float4*)(Ag1 + ko);
      pb0 = *(const float4*)(Bg0 + ko * N);
      pb1 = *(const float4*)(Bg1 + ko * N);
    }
#pragma unroll
    for (int kk = 0; kk < BK; kk += 8) {
      uint32_t af[2][4];
#pragma unroll
      for (int mf = 0; mf < 2; ++mf) {
        const float* ap = &As[cur][(wm + mf * 16 + grp) * ASTR + kk + tig];
        af[mf][0] = __float_as_uint(ap[0]);
        af[mf][1] = __float_as_uint(ap[8 * ASTR]);
        af[mf][2] = __float_as_uint(ap[4]);
        af[mf][3] = __float_as_uint(ap[8 * ASTR + 4]);
      }
#pragma unroll
      for (int nf = 0; nf < 8; ++nf) {
        const float* bp = &Bs[cur][(kk + tig) * BSTR + wn + nf * 8 + grp];
        uint32_t bf[2];
        bf[0] = __float_as_uint(bp[0]);
        bf[1] = __float_as_uint(bp[4 * BSTR]);
        mma8(acc[0][nf], af[0], bf);
        mma8(acc[1][nf], af[1], bf);
      }
    }
    if (t + 1 < nT) {
      const int nxt = cur ^ 1;
      *(float4*)&As[nxt][lr * ASTR + lc]        = tf32r4(pa0);
      *(float4*)&As[nxt][(lr + 64) * ASTR + lc] = tf32r4(pa1);
      *(float4*)&Bs[nxt][bk * BSTR + bc]        = tf32r4(pb0);
      *(float4*)&Bs[nxt][(bk + 8) * BSTR + bc]  = tf32r4(pb1);
      __syncthreads();
      cur = nxt;
    }
  }

#pragma unroll
  for (int mf = 0; mf < 2; ++mf)
#pragma unroll
    for (int nf = 0; nf < 8; ++nf) {
      const int r = row0 + wm + mf * 16 + grp;
      const int c = col0 + wn + nf * 8 + tig * 2;
      float* cp = C + (size_t)r * N + c;
      cp[0] = acc[mf][nf][0];
      cp[1] = acc[mf][nf][1];
      cp[(size_t)8 * N]     = acc[mf][nf][2];
      cp[(size_t)8 * N + 1] = acc[mf][nf][3];
    }
}

// ---------------------------------------------------------------------------

extern "C" void kernel_launch(void* const* d_in, const int* in_sizes, int n_in,
                              void* d_out, int out_size) {
  (void)in_sizes; (void)n_in; (void)out_size;
  const float* x  = (const float*)d_in[0];
  const float* y  = (const float*)d_in[1];
  const float* Wq = (const float*)d_in[2];
  const float* Wk = (const float*)d_in[3];
  const float* Wv = (const float*)d_in[4];
  float* out = (float*)d_out;

  float *q, *k, *v, *a;
  cudaGetSymbolAddress((void**)&q, g_q);
  cudaGetSymbolAddress((void**)&k, g_k);
  cudaGetSymbolAddress((void**)&v, g_v);
  cudaGetSymbolAddress((void**)&a, g_a);

  dim3 blk(256, 1, 1);

  // Stage 1: projections
  dim3 gQKV(kD / BN, kNX / BM, 1);
  gemm_nt<0><<<gQKV, blk>>>(x, Wq, q, kNX, kD, kC, 1.0f);
  gemm_nt<0><<<gQKV, blk>>>(y, Wk, k, kNY, kD, kC, 1.0f);
  gemm_nt<0><<<gQKV, blk>>>(y, Wv, v, kNY, kD, kC, 1.0f);

  // Stage 2: a = mask(q k^T) / sqrt(D), lower blocks only
  dim3 gA(kNY / BN, kNX / BM, 1);
  const float scale = 1.0f / sqrtf((float)kD);
  gemm_nt<1><<<gA, blk>>>(q, k, a, kNX, kNY, kD, scale);

  // Stage 3: out = a v  (K limited to written blocks per row-block)
  dim3 gO(kD / BN, kNX / BM, 1);
  gemm_nn<1><<<gO, blk>>>(a, v, out, kNX, kD, kNY);
}